// round 1
// baseline (speedup 1.0000x reference)
#include <cuda_runtime.h>
#include <math.h>

#define DIM 1024
#define HIDDEN 2048
#define NE 8
#define TOKENS 2048
#define NSLOT (2*TOKENS)

// ---------------- scratch (static device globals; no runtime alloc) ----------
__device__ int   g_cnt[NE];
__device__ int   g_slots[NE * TOKENS];          // per-expert slot lists
__device__ float g_w[NSLOT];                    // combine weight per slot
__device__ float g_h2[(size_t)NSLOT * HIDDEN];  // relu^2 activations (32 MB)
__device__ float g_y[(size_t)NSLOT * DIM];      // per-slot expert outputs (16 MB)

// ---------------- zero expert counters ---------------------------------------
__global__ void zero_cnt_kernel() {
    if (threadIdx.x < NE) g_cnt[threadIdx.x] = 0;
}

// ---------------- router: logits -> softmax -> top2 -> renorm -> lists -------
__global__ void router_kernel(const float* __restrict__ x,
                              const float* __restrict__ Wr) {
    int warp = threadIdx.x >> 5;
    int lane = threadIdx.x & 31;
    int t = blockIdx.x * 8 + warp;
    if (t >= TOKENS) return;

    float acc[NE];
#pragma unroll
    for (int e = 0; e < NE; e++) acc[e] = 0.f;

    const float* xr = x + (size_t)t * DIM;
    for (int d = lane; d < DIM; d += 32) {
        float xv = xr[d];
#pragma unroll
        for (int e = 0; e < NE; e++) acc[e] += xv * Wr[e * DIM + d];
    }
#pragma unroll
    for (int e = 0; e < NE; e++) {
#pragma unroll
        for (int o = 16; o > 0; o >>= 1)
            acc[e] += __shfl_xor_sync(0xffffffffu, acc[e], o);
    }

    if (lane == 0) {
        float mx = acc[0];
#pragma unroll
        for (int e = 1; e < NE; e++) mx = fmaxf(mx, acc[e]);
        float p[NE];
        float Z = 0.f;
#pragma unroll
        for (int e = 0; e < NE; e++) { p[e] = expf(acc[e] - mx); Z += p[e]; }

        int i1 = 0; float b1 = -1.f;
#pragma unroll
        for (int e = 0; e < NE; e++) { if (p[e] > b1) { b1 = p[e]; i1 = e; } }
        int i2 = -1; float b2 = -1.f;
#pragma unroll
        for (int e = 0; e < NE; e++) { if (e != i1 && p[e] > b2) { b2 = p[e]; i2 = e; } }

        float p1 = b1 / Z, p2 = b2 / Z;
        float s = p1 + p2 + 1e-8f;
        float w1 = p1 / s, w2 = p2 / s;

        int pos1 = atomicAdd(&g_cnt[i1], 1);
        g_slots[i1 * TOKENS + pos1] = 2 * t;
        g_w[2 * t] = w1;
        int pos2 = atomicAdd(&g_cnt[i2], 1);
        g_slots[i2 * TOKENS + pos2] = 2 * t + 1;
        g_w[2 * t + 1] = w2;
    }
}

// ---------------- grouped SGEMM ----------------------------------------------
// MODE 0 (fc):   A = x gathered via token=slot>>1 (lda=DIM),   C = g_h2 (ldc=HIDDEN),
//                epilogue relu^2. N=HIDDEN, K=DIM.
// MODE 1 (proj): A = g_h2 rows = slot (lda=HIDDEN),            C = g_y (ldc=DIM),
//                epilogue *g_w[slot]. N=DIM, K=HIDDEN.
// Tile: 64x64xBK32, 256 threads, 4x4 per-thread register block.
template <int K, int N, int LDA, int LDC, int MODE>
__global__ void __launch_bounds__(256) moe_gemm(const float* __restrict__ X,
                                                const float* __restrict__ W) {
    const int e   = blockIdx.z;
    const int cnt = g_cnt[e];
    const int m0  = blockIdx.y * 64;
    if (m0 >= cnt) return;
    const int n0  = blockIdx.x * 64;
    const int* slots = g_slots + e * TOKENS;

    const float* Abase = (MODE == 0) ? X : g_h2;
    float*       Cbase = (MODE == 0) ? g_h2 : g_y;

    __shared__ float As[32][64];
    __shared__ float Bs[32][64];

    const int tid  = threadIdx.x;
    const int ldr  = tid >> 3;   // loader row 0..31
    const int ldc4 = tid & 7;    // loader float4 col 0..7
    const int tx   = tid & 15;
    const int ty   = tid >> 4;

    // A row pointers for the two loader passes
    const float* aptr[2];
    bool aval[2];
#pragma unroll
    for (int p = 0; p < 2; p++) {
        int m = m0 + ldr + p * 32;
        if (m < cnt) {
            int slot = slots[m];
            int arow = (MODE == 0) ? (slot >> 1) : slot;
            aptr[p] = Abase + (size_t)arow * LDA + ldc4 * 4;
            aval[p] = true;
        } else {
            aptr[p] = Abase;
            aval[p] = false;
        }
    }
    const float* bptr = W + (size_t)e * N * K + (size_t)n0 * K + ldc4 * 4;

    float acc[4][4];
#pragma unroll
    for (int i = 0; i < 4; i++)
#pragma unroll
        for (int j = 0; j < 4; j++) acc[i][j] = 0.f;

    for (int kt = 0; kt < K; kt += 32) {
#pragma unroll
        for (int p = 0; p < 2; p++) {
            int r = ldr + p * 32;
            float4 v = aval[p] ? *(const float4*)(aptr[p] + kt)
                               : make_float4(0.f, 0.f, 0.f, 0.f);
            As[ldc4 * 4 + 0][r] = v.x;
            As[ldc4 * 4 + 1][r] = v.y;
            As[ldc4 * 4 + 2][r] = v.z;
            As[ldc4 * 4 + 3][r] = v.w;
        }
#pragma unroll
        for (int p = 0; p < 2; p++) {
            int r = ldr + p * 32;
            float4 v = *(const float4*)(bptr + (size_t)r * K + kt);
            Bs[ldc4 * 4 + 0][r] = v.x;
            Bs[ldc4 * 4 + 1][r] = v.y;
            Bs[ldc4 * 4 + 2][r] = v.z;
            Bs[ldc4 * 4 + 3][r] = v.w;
        }
        __syncthreads();

#pragma unroll
        for (int k = 0; k < 32; k++) {
            float4 a = *(const float4*)&As[k][ty * 4];
            float4 b = *(const float4*)&Bs[k][tx * 4];
            acc[0][0] += a.x * b.x; acc[0][1] += a.x * b.y;
            acc[0][2] += a.x * b.z; acc[0][3] += a.x * b.w;
            acc[1][0] += a.y * b.x; acc[1][1] += a.y * b.y;
            acc[1][2] += a.y * b.z; acc[1][3] += a.y * b.w;
            acc[2][0] += a.z * b.x; acc[2][1] += a.z * b.y;
            acc[2][2] += a.z * b.z; acc[2][3] += a.z * b.w;
            acc[3][0] += a.w * b.x; acc[3][1] += a.w * b.y;
            acc[3][2] += a.w * b.z; acc[3][3] += a.w * b.w;
        }
        __syncthreads();
    }

#pragma unroll
    for (int i = 0; i < 4; i++) {
        int m = m0 + ty * 4 + i;
        if (m >= cnt) break;
        int slot = slots[m];
        float* crow = Cbase + (size_t)slot * LDC + n0 + tx * 4;
        if (MODE == 0) {
#pragma unroll
            for (int j = 0; j < 4; j++) {
                float r = fmaxf(acc[i][j], 0.f);
                crow[j] = r * r;
            }
        } else {
            float w = g_w[slot];
#pragma unroll
            for (int j = 0; j < 4; j++) crow[j] = w * acc[i][j];
        }
    }
}

// ---------------- combine: out[t] = y[2t] + y[2t+1]; zero aux-loss tail ------
__global__ void combine_kernel(float* __restrict__ out, int out_size) {
    int idx = blockIdx.x * blockDim.x + threadIdx.x;
    if (idx >= out_size) return;
    if (idx < TOKENS * DIM) {
        int t = idx >> 10;          // DIM = 1024
        int d = idx & 1023;
        out[idx] = g_y[((size_t)(2 * t)) * DIM + d] +
                   g_y[((size_t)(2 * t + 1)) * DIM + d];
    } else {
        out[idx] = 0.f;  // aux_loss = 0 in eval mode
    }
}

// ---------------- launch ------------------------------------------------------
extern "C" void kernel_launch(void* const* d_in, const int* in_sizes, int n_in,
                              void* d_out, int out_size) {
    const float* x   = (const float*)d_in[0];
    const float* Wr  = (const float*)d_in[1];
    const float* Wfc = (const float*)d_in[2];
    const float* Wpj = (const float*)d_in[3];
    float* out = (float*)d_out;

    zero_cnt_kernel<<<1, 32>>>();
    router_kernel<<<TOKENS / 8, 256>>>(x, Wr);

    // fc: M<=cnt[e], N=HIDDEN(2048), K=DIM(1024)
    moe_gemm<DIM, HIDDEN, DIM, HIDDEN, 0>
        <<<dim3(HIDDEN / 64, TOKENS / 64, NE), 256>>>(x, Wfc);

    // proj: N=DIM(1024), K=HIDDEN(2048)
    moe_gemm<HIDDEN, DIM, HIDDEN, DIM, 1>
        <<<dim3(DIM / 64, TOKENS / 64, NE), 256>>>(x, Wpj);

    combine_kernel<<<(out_size + 255) / 256, 256>>>(out, out_size);
}

// round 4
// speedup vs baseline: 3.1966x; 3.1966x over previous
#include <cuda_runtime.h>
#include <cuda_bf16.h>
#include <math.h>
#include <stdint.h>

#define DIM 1024
#define HIDDEN 2048
#define NE 8
#define TOKENS 2048
#define NSLOT (2*TOKENS)

// ---------------- scratch (static device globals; no runtime alloc) ----------
__device__ int   g_cnt[NE];
__device__ int   g_slots[NE * TOKENS];
__device__ float g_w[NSLOT];
__device__ float g_y[(size_t)NSLOT * DIM];                      // 16 MB

__device__ __nv_bfloat16 g_xhi[(size_t)TOKENS * DIM];
__device__ __nv_bfloat16 g_xlo[(size_t)TOKENS * DIM];
__device__ __nv_bfloat16 g_wfchi[(size_t)NE * HIDDEN * DIM];
__device__ __nv_bfloat16 g_wfclo[(size_t)NE * HIDDEN * DIM];
__device__ __nv_bfloat16 g_wpjhi[(size_t)NE * DIM * HIDDEN];
__device__ __nv_bfloat16 g_wpjlo[(size_t)NE * DIM * HIDDEN];
__device__ __nv_bfloat16 g_h2hi[(size_t)NSLOT * HIDDEN];
__device__ __nv_bfloat16 g_h2lo[(size_t)NSLOT * HIDDEN];

// ---------------- helpers -----------------------------------------------------
__device__ __forceinline__ uint32_t smem_u32(const void* p) {
    uint32_t a;
    asm("{ .reg .u64 t; cvta.to.shared.u64 t, %1; cvt.u32.u64 %0, t; }"
        : "=r"(a) : "l"(p));
    return a;
}
__device__ __forceinline__ uint32_t sw128(uint32_t b) { return b ^ ((b >> 3) & 0x70); }

__device__ __forceinline__ void ldm_x4(uint32_t* r, uint32_t addr) {
    asm volatile("ldmatrix.sync.aligned.m8n8.x4.shared.b16 {%0,%1,%2,%3}, [%4];"
                 : "=r"(r[0]), "=r"(r[1]), "=r"(r[2]), "=r"(r[3]) : "r"(addr));
}
__device__ __forceinline__ void mma_bf16(float* d, const uint32_t* a, const uint32_t* b) {
    asm volatile(
        "mma.sync.aligned.m16n8k16.row.col.f32.bf16.bf16.f32 "
        "{%0,%1,%2,%3}, {%4,%5,%6,%7}, {%8,%9}, {%0,%1,%2,%3};"
        : "+f"(d[0]), "+f"(d[1]), "+f"(d[2]), "+f"(d[3])
        : "r"(a[0]), "r"(a[1]), "r"(a[2]), "r"(a[3]), "r"(b[0]), "r"(b[1]));
}

// ---------------- zero counters ----------------------------------------------
__global__ void zero_cnt_kernel() {
    if (threadIdx.x < NE) g_cnt[threadIdx.x] = 0;
}

// ---------------- fp32 -> bf16 hi/lo split -----------------------------------
// WHICH: 0 = x, 1 = W_fc, 2 = W_proj
template <int WHICH>
__global__ void split_kernel(const float* __restrict__ src, int n4) {
    __nv_bfloat16* hi = (WHICH == 0) ? g_xhi : (WHICH == 1) ? g_wfchi : g_wpjhi;
    __nv_bfloat16* lo = (WHICH == 0) ? g_xlo : (WHICH == 1) ? g_wfclo : g_wpjlo;
    int i = blockIdx.x * blockDim.x + threadIdx.x;
    if (i >= n4) return;
    float4 v = ((const float4*)src)[i];
    __nv_bfloat16 h0 = __float2bfloat16(v.x);
    __nv_bfloat16 h1 = __float2bfloat16(v.y);
    __nv_bfloat16 h2 = __float2bfloat16(v.z);
    __nv_bfloat16 h3 = __float2bfloat16(v.w);
    __nv_bfloat16 l0 = __float2bfloat16(v.x - __bfloat162float(h0));
    __nv_bfloat16 l1 = __float2bfloat16(v.y - __bfloat162float(h1));
    __nv_bfloat16 l2 = __float2bfloat16(v.z - __bfloat162float(h2));
    __nv_bfloat16 l3 = __float2bfloat16(v.w - __bfloat162float(h3));
    __nv_bfloat162* hp = (__nv_bfloat162*)(hi + (size_t)i * 4);
    __nv_bfloat162* lp = (__nv_bfloat162*)(lo + (size_t)i * 4);
    hp[0] = __nv_bfloat162(h0, h1); hp[1] = __nv_bfloat162(h2, h3);
    lp[0] = __nv_bfloat162(l0, l1); lp[1] = __nv_bfloat162(l2, l3);
}

// ---------------- router ------------------------------------------------------
__global__ void router_kernel(const float* __restrict__ x,
                              const float* __restrict__ Wr) {
    int warp = threadIdx.x >> 5;
    int lane = threadIdx.x & 31;
    int t = blockIdx.x * 8 + warp;
    if (t >= TOKENS) return;

    float acc[NE];
#pragma unroll
    for (int e = 0; e < NE; e++) acc[e] = 0.f;
    const float* xr = x + (size_t)t * DIM;
    for (int d = lane; d < DIM; d += 32) {
        float xv = xr[d];
#pragma unroll
        for (int e = 0; e < NE; e++) acc[e] += xv * Wr[e * DIM + d];
    }
#pragma unroll
    for (int e = 0; e < NE; e++) {
#pragma unroll
        for (int o = 16; o > 0; o >>= 1)
            acc[e] += __shfl_xor_sync(0xffffffffu, acc[e], o);
    }
    if (lane == 0) {
        float mx = acc[0];
#pragma unroll
        for (int e = 1; e < NE; e++) mx = fmaxf(mx, acc[e]);
        float p[NE]; float Z = 0.f;
#pragma unroll
        for (int e = 0; e < NE; e++) { p[e] = expf(acc[e] - mx); Z += p[e]; }
        int i1 = 0; float b1 = -1.f;
#pragma unroll
        for (int e = 0; e < NE; e++) if (p[e] > b1) { b1 = p[e]; i1 = e; }
        int i2 = -1; float b2 = -1.f;
#pragma unroll
        for (int e = 0; e < NE; e++) if (e != i1 && p[e] > b2) { b2 = p[e]; i2 = e; }
        float p1 = b1 / Z, p2 = b2 / Z;
        float s = p1 + p2 + 1e-8f;
        int pos1 = atomicAdd(&g_cnt[i1], 1);
        g_slots[i1 * TOKENS + pos1] = 2 * t;
        g_w[2 * t] = p1 / s;
        int pos2 = atomicAdd(&g_cnt[i2], 1);
        g_slots[i2 * TOKENS + pos2] = 2 * t + 1;
        g_w[2 * t + 1] = p2 / s;
    }
}

// ---------------- HMMA grouped GEMM ------------------------------------------
// C[128,128] fp32 = sum_K A*B with bf16 2-term split: hi*hi + hi*lo + lo*hi.
// SMEM tiles: 128 rows x 64 bf16 (128B rows, SW128 swizzle). 512 thr, 16 warps
// of 32x32 warp tiles. Register-prefetch software pipeline over K (step 64).
// MODE 0 (fc):   A = x[slot>>1],  K=DIM,   B = g_wfchi/lo,  epi relu^2 -> h2
// MODE 1 (proj): A = h2[slot],    K=HIDDEN,B = g_wpjhi/lo,  epi *g_w -> g_y
#define OFF_AHI 0
#define OFF_ALO 16384
#define OFF_BHI 32768
#define OFF_BLO 49152
#define SMEM_TOTAL 65536

template <int K, int NTOT, int MODE>
__global__ void __launch_bounds__(512, 1) moe_mma_gemm() {
    const int e = blockIdx.z;
    const int cnt = g_cnt[e];
    const int m0 = blockIdx.y * 128;
    if (m0 >= cnt) return;
    const int n0 = blockIdx.x * 128;
    const int* slots = g_slots + e * TOKENS;

    extern __shared__ char smem[];
    const uint32_t sb = smem_u32(smem);
    const int tid = threadIdx.x;
    const int lane = tid & 31;
    const int wid = tid >> 5;
    const int wm = wid & 3;       // m-block of 32
    const int wn = wid >> 2;      // n-block of 32

    const __nv_bfloat16* Ahi_base = (MODE == 0) ? g_xhi : g_h2hi;
    const __nv_bfloat16* Alo_base = (MODE == 0) ? g_xlo : g_h2lo;
    const __nv_bfloat16* Bhi_base = (MODE == 0) ? g_wfchi : g_wpjhi;
    const __nv_bfloat16* Blo_base = (MODE == 0) ? g_wfclo : g_wpjlo;

    // loader: thread covers rows r0l and r0l+64, 16B chunk c16 of 128B row
    const int c16 = tid & 7;
    const int r0l = tid >> 3;  // 0..63

    const __nv_bfloat16* aphi[2];
    const __nv_bfloat16* aplo[2];
    const __nv_bfloat16* bphi[2];
    const __nv_bfloat16* bplo[2];
    bool aval[2];
    uint32_t swoff[2];
#pragma unroll
    for (int p = 0; p < 2; p++) {
        int row = r0l + 64 * p;
        swoff[p] = sw128((uint32_t)(row * 128 + c16 * 16));
        int m = m0 + row;
        if (m < cnt) {
            int slot = slots[m];
            int arow = (MODE == 0) ? (slot >> 1) : slot;
            aphi[p] = Ahi_base + (size_t)arow * K + c16 * 8;
            aplo[p] = Alo_base + (size_t)arow * K + c16 * 8;
            aval[p] = true;
        } else {
            aphi[p] = Ahi_base; aplo[p] = Alo_base; aval[p] = false;
        }
        size_t boff = ((size_t)e * NTOT + n0 + row) * K + c16 * 8;
        bphi[p] = Bhi_base + boff;
        bplo[p] = Blo_base + boff;
    }

    // ldmatrix address components (within-tile byte offsets before swizzle)
    const uint32_t a_row = wm * 32 + (lane & 15);
    const uint32_t a_kb = (uint32_t)((lane >> 4) << 4);
    const uint32_t b_row = wn * 32 + (lane & 7) + ((lane >> 4) << 3);
    const uint32_t b_kb = (uint32_t)(((lane >> 3) & 1) << 4);

    float acc[2][4][4];
#pragma unroll
    for (int i = 0; i < 2; i++)
#pragma unroll
        for (int j = 0; j < 4; j++)
#pragma unroll
            for (int q = 0; q < 4; q++) acc[i][j][q] = 0.f;

    // prefetch k-slab 0
    float4 pah[2], pal[2], pbh[2], pbl[2];
#pragma unroll
    for (int p = 0; p < 2; p++) {
        pah[p] = aval[p] ? *(const float4*)(aphi[p]) : make_float4(0, 0, 0, 0);
        pal[p] = aval[p] ? *(const float4*)(aplo[p]) : make_float4(0, 0, 0, 0);
        pbh[p] = *(const float4*)(bphi[p]);
        pbl[p] = *(const float4*)(bplo[p]);
    }

    for (int kt = 0; kt < K; kt += 64) {
#pragma unroll
        for (int p = 0; p < 2; p++) {
            *(float4*)(smem + OFF_AHI + swoff[p]) = pah[p];
            *(float4*)(smem + OFF_ALO + swoff[p]) = pal[p];
            *(float4*)(smem + OFF_BHI + swoff[p]) = pbh[p];
            *(float4*)(smem + OFF_BLO + swoff[p]) = pbl[p];
        }
        __syncthreads();

        if (kt + 64 < K) {
            int kn = kt + 64;
#pragma unroll
            for (int p = 0; p < 2; p++) {
                pah[p] = aval[p] ? *(const float4*)(aphi[p] + kn) : make_float4(0, 0, 0, 0);
                pal[p] = aval[p] ? *(const float4*)(aplo[p] + kn) : make_float4(0, 0, 0, 0);
                pbh[p] = *(const float4*)(bphi[p] + kn);
                pbl[p] = *(const float4*)(bplo[p] + kn);
            }
        }

#pragma unroll
        for (int c = 0; c < 4; c++) {
            const uint32_t kb = (uint32_t)(c * 32);
            uint32_t ah[2][4], al[2][4], bh[2][4], bl[2][4];
#pragma unroll
            for (int i = 0; i < 2; i++) {
                uint32_t off = sw128((a_row + 16 * i) * 128 + kb + a_kb);
                ldm_x4(ah[i], sb + OFF_AHI + off);
                ldm_x4(al[i], sb + OFF_ALO + off);
            }
#pragma unroll
            for (int jj = 0; jj < 2; jj++) {
                uint32_t off = sw128((b_row + 16 * jj) * 128 + kb + b_kb);
                ldm_x4(bh[jj], sb + OFF_BHI + off);
                ldm_x4(bl[jj], sb + OFF_BLO + off);
            }
#pragma unroll
            for (int i = 0; i < 2; i++)
#pragma unroll
                for (int j = 0; j < 4; j++) {
                    const uint32_t* bhp = &bh[j >> 1][(j & 1) * 2];
                    const uint32_t* blp = &bl[j >> 1][(j & 1) * 2];
                    mma_bf16(acc[i][j], ah[i], bhp);
                    mma_bf16(acc[i][j], ah[i], blp);
                    mma_bf16(acc[i][j], al[i], bhp);
                }
        }
        __syncthreads();
    }

    // epilogue
    const int gid = lane >> 2;
    const int tig = lane & 3;
#pragma unroll
    for (int i = 0; i < 2; i++) {
#pragma unroll
        for (int h = 0; h < 2; h++) {
            int mrow = m0 + wm * 32 + i * 16 + gid + 8 * h;
            if (mrow >= cnt) continue;
            int slot = slots[mrow];
            if (MODE == 0) {
                __nv_bfloat16* hr = g_h2hi + (size_t)slot * HIDDEN + n0;
                __nv_bfloat16* lr = g_h2lo + (size_t)slot * HIDDEN + n0;
#pragma unroll
                for (int j = 0; j < 4; j++) {
                    int col = wn * 32 + j * 8 + 2 * tig;
#pragma unroll
                    for (int q = 0; q < 2; q++) {
                        float v = acc[i][j][h * 2 + q];
                        v = fmaxf(v, 0.f);
                        v = v * v;
                        __nv_bfloat16 hh = __float2bfloat16(v);
                        __nv_bfloat16 ll = __float2bfloat16(v - __bfloat162float(hh));
                        hr[col + q] = hh;
                        lr[col + q] = ll;
                    }
                }
            } else {
                float wgt = g_w[slot];
                float* yr = g_y + (size_t)slot * DIM + n0;
#pragma unroll
                for (int j = 0; j < 4; j++) {
                    int col = wn * 32 + j * 8 + 2 * tig;
                    yr[col + 0] = wgt * acc[i][j][h * 2 + 0];
                    yr[col + 1] = wgt * acc[i][j][h * 2 + 1];
                }
            }
        }
    }
}

// ---------------- combine -----------------------------------------------------
__global__ void combine_kernel(float* __restrict__ out, int out_size) {
    int idx = blockIdx.x * blockDim.x + threadIdx.x;
    if (idx >= out_size) return;
    if (idx < TOKENS * DIM) {
        int t = idx >> 10;
        int d = idx & 1023;
        out[idx] = g_y[((size_t)(2 * t)) * DIM + d] +
                   g_y[((size_t)(2 * t + 1)) * DIM + d];
    } else {
        out[idx] = 0.f;
    }
}

// ---------------- launch ------------------------------------------------------
extern "C" void kernel_launch(void* const* d_in, const int* in_sizes, int n_in,
                              void* d_out, int out_size) {
    const float* x = (const float*)d_in[0];
    const float* Wr = (const float*)d_in[1];
    const float* Wfc = (const float*)d_in[2];
    const float* Wpj = (const float*)d_in[3];
    float* out = (float*)d_out;

    cudaFuncSetAttribute(moe_mma_gemm<DIM, HIDDEN, 0>,
                         cudaFuncAttributeMaxDynamicSharedMemorySize, SMEM_TOTAL);
    cudaFuncSetAttribute(moe_mma_gemm<HIDDEN, DIM, 1>,
                         cudaFuncAttributeMaxDynamicSharedMemorySize, SMEM_TOTAL);

    zero_cnt_kernel<<<1, 32>>>();
    router_kernel<<<TOKENS / 8, 256>>>(x, Wr);

    int n4x = TOKENS * DIM / 4;
    int n4w = NE * HIDDEN * DIM / 4;
    split_kernel<0><<<(n4x + 255) / 256, 256>>>(x, n4x);
    split_kernel<1><<<(n4w + 255) / 256, 256>>>(Wfc, n4w);
    split_kernel<2><<<(n4w + 255) / 256, 256>>>(Wpj, n4w);

    // fc: N=HIDDEN, K=DIM
    moe_mma_gemm<DIM, HIDDEN, 0>
        <<<dim3(HIDDEN / 128, TOKENS / 128, NE), 512, SMEM_TOTAL>>>();
    // proj: N=DIM, K=HIDDEN
    moe_mma_gemm<HIDDEN, DIM, 1>
        <<<dim3(DIM / 128, TOKENS / 128, NE), 512, SMEM_TOTAL>>>();

    combine_kernel<<<(out_size + 255) / 256, 256>>>(out, out_size);
}

// round 5
// speedup vs baseline: 3.4243x; 1.0712x over previous
#include <cuda_runtime.h>
#include <cuda_bf16.h>
#include <math.h>
#include <stdint.h>

#define DIM 1024
#define HIDDEN 2048
#define NE 8
#define TOKENS 2048
#define NSLOT (2*TOKENS)

// ---------------- scratch (static device globals; no runtime alloc) ----------
__device__ int   g_cnt[NE];
__device__ int   g_slots[NE * TOKENS];
__device__ float g_w[NSLOT];

__device__ __nv_bfloat16 g_xhi[(size_t)TOKENS * DIM];
__device__ __nv_bfloat16 g_xlo[(size_t)TOKENS * DIM];
__device__ __nv_bfloat16 g_wfchi[(size_t)NE * HIDDEN * DIM];
__device__ __nv_bfloat16 g_wfclo[(size_t)NE * HIDDEN * DIM];
__device__ __nv_bfloat16 g_wpjhi[(size_t)NE * DIM * HIDDEN];
__device__ __nv_bfloat16 g_wpjlo[(size_t)NE * DIM * HIDDEN];
__device__ __nv_bfloat16 g_h2hi[(size_t)NSLOT * HIDDEN];
__device__ __nv_bfloat16 g_h2lo[(size_t)NSLOT * HIDDEN];

// ---------------- helpers -----------------------------------------------------
__device__ __forceinline__ uint32_t smem_u32(const void* p) {
    uint32_t a;
    asm("{ .reg .u64 t; cvta.to.shared.u64 t, %1; cvt.u32.u64 %0, t; }"
        : "=r"(a) : "l"(p));
    return a;
}
__device__ __forceinline__ uint32_t sw128(uint32_t b) { return b ^ ((b >> 3) & 0x70); }

__device__ __forceinline__ void ldm_x4(uint32_t* r, uint32_t addr) {
    asm volatile("ldmatrix.sync.aligned.m8n8.x4.shared.b16 {%0,%1,%2,%3}, [%4];"
                 : "=r"(r[0]), "=r"(r[1]), "=r"(r[2]), "=r"(r[3]) : "r"(addr));
}
__device__ __forceinline__ void mma_bf16(float* d, const uint32_t* a, const uint32_t* b) {
    asm volatile(
        "mma.sync.aligned.m16n8k16.row.col.f32.bf16.bf16.f32 "
        "{%0,%1,%2,%3}, {%4,%5,%6,%7}, {%8,%9}, {%0,%1,%2,%3};"
        : "+f"(d[0]), "+f"(d[1]), "+f"(d[2]), "+f"(d[3])
        : "r"(a[0]), "r"(a[1]), "r"(a[2]), "r"(a[3]), "r"(b[0]), "r"(b[1]));
}
__device__ __forceinline__ void cp16(uint32_t dst, const void* src, uint32_t srcsize) {
    asm volatile("cp.async.cg.shared.global [%0], [%1], 16, %2;"
                 :: "r"(dst), "l"(src), "r"(srcsize) : "memory");
}
__device__ __forceinline__ void cp_commit() {
    asm volatile("cp.async.commit_group;" ::: "memory");
}
template <int N>
__device__ __forceinline__ void cp_wait() {
    asm volatile("cp.async.wait_group %0;" :: "n"(N) : "memory");
}

// ---------------- zero counters / zero output --------------------------------
__global__ void zero_cnt_kernel() {
    if (threadIdx.x < NE) g_cnt[threadIdx.x] = 0;
}
__global__ void zero_out_kernel(float* __restrict__ out, int out_size) {
    int i = blockIdx.x * blockDim.x + threadIdx.x;
    int n4 = out_size >> 2;
    if (i < n4) ((float4*)out)[i] = make_float4(0.f, 0.f, 0.f, 0.f);
    if (i == 0) {
        for (int j = n4 << 2; j < out_size; j++) out[j] = 0.f;
    }
}

// ---------------- fp32 -> bf16 hi/lo split -----------------------------------
template <int WHICH>  // 0 = x, 1 = W_fc, 2 = W_proj
__global__ void split_kernel(const float* __restrict__ src, int n4) {
    __nv_bfloat16* hi = (WHICH == 0) ? g_xhi : (WHICH == 1) ? g_wfchi : g_wpjhi;
    __nv_bfloat16* lo = (WHICH == 0) ? g_xlo : (WHICH == 1) ? g_wfclo : g_wpjlo;
    int i = blockIdx.x * blockDim.x + threadIdx.x;
    if (i >= n4) return;
    float4 v = ((const float4*)src)[i];
    __nv_bfloat16 h0 = __float2bfloat16(v.x);
    __nv_bfloat16 h1 = __float2bfloat16(v.y);
    __nv_bfloat16 h2 = __float2bfloat16(v.z);
    __nv_bfloat16 h3 = __float2bfloat16(v.w);
    __nv_bfloat16 l0 = __float2bfloat16(v.x - __bfloat162float(h0));
    __nv_bfloat16 l1 = __float2bfloat16(v.y - __bfloat162float(h1));
    __nv_bfloat16 l2 = __float2bfloat16(v.z - __bfloat162float(h2));
    __nv_bfloat16 l3 = __float2bfloat16(v.w - __bfloat162float(h3));
    __nv_bfloat162* hp = (__nv_bfloat162*)(hi + (size_t)i * 4);
    __nv_bfloat162* lp = (__nv_bfloat162*)(lo + (size_t)i * 4);
    hp[0] = __nv_bfloat162(h0, h1); hp[1] = __nv_bfloat162(h2, h3);
    lp[0] = __nv_bfloat162(l0, l1); lp[1] = __nv_bfloat162(l2, l3);
}

// ---------------- router ------------------------------------------------------
__global__ void router_kernel(const float* __restrict__ x,
                              const float* __restrict__ Wr) {
    int warp = threadIdx.x >> 5;
    int lane = threadIdx.x & 31;
    int t = blockIdx.x * 8 + warp;
    if (t >= TOKENS) return;

    float acc[NE];
#pragma unroll
    for (int e = 0; e < NE; e++) acc[e] = 0.f;
    const float* xr = x + (size_t)t * DIM;
    for (int d = lane; d < DIM; d += 32) {
        float xv = xr[d];
#pragma unroll
        for (int e = 0; e < NE; e++) acc[e] += xv * Wr[e * DIM + d];
    }
#pragma unroll
    for (int e = 0; e < NE; e++) {
#pragma unroll
        for (int o = 16; o > 0; o >>= 1)
            acc[e] += __shfl_xor_sync(0xffffffffu, acc[e], o);
    }
    if (lane == 0) {
        float mx = acc[0];
#pragma unroll
        for (int e = 1; e < NE; e++) mx = fmaxf(mx, acc[e]);
        float p[NE]; float Z = 0.f;
#pragma unroll
        for (int e = 0; e < NE; e++) { p[e] = expf(acc[e] - mx); Z += p[e]; }
        int i1 = 0; float b1 = -1.f;
#pragma unroll
        for (int e = 0; e < NE; e++) if (p[e] > b1) { b1 = p[e]; i1 = e; }
        int i2 = -1; float b2 = -1.f;
#pragma unroll
        for (int e = 0; e < NE; e++) if (e != i1 && p[e] > b2) { b2 = p[e]; i2 = e; }
        float p1 = b1 / Z, p2 = b2 / Z;
        float s = p1 + p2 + 1e-8f;
        int pos1 = atomicAdd(&g_cnt[i1], 1);
        g_slots[i1 * TOKENS + pos1] = 2 * t;
        g_w[2 * t] = p1 / s;
        int pos2 = atomicAdd(&g_cnt[i2], 1);
        g_slots[i2 * TOKENS + pos2] = 2 * t + 1;
        g_w[2 * t + 1] = p2 / s;
    }
}

// ---------------- HMMA grouped GEMM (double-buffered cp.async) ----------------
// C[128,128] fp32 = sum_K A*B with bf16 2-term split: hi*hi + hi*lo + lo*hi.
// 2-stage cp.async pipeline, stage = 4 tiles x 16KB (128 rows x 128B, SW128).
// 512 thr, 16 warps of 32x32 warp tiles.
// MODE 0 (fc):   A = x[slot>>1],  K=DIM,   B = W_fc,  epi relu^2 -> h2 hi/lo
// MODE 1 (proj): A = h2[slot],    K=HIDDEN,B = W_proj, epi wgt*acc atomicAdd-> out
#define OFF_AHI 0
#define OFF_ALO 16384
#define OFF_BHI 32768
#define OFF_BLO 49152
#define STAGE_BYTES 65536
#define SMEM_TOTAL (2 * STAGE_BYTES)

template <int K, int NTOT, int MODE>
__global__ void __launch_bounds__(512, 1) moe_mma_gemm(float* __restrict__ out) {
    const int e = blockIdx.z;
    const int cnt = g_cnt[e];
    const int m0 = blockIdx.y * 128;
    if (m0 >= cnt) return;
    const int n0 = blockIdx.x * 128;
    const int* slots = g_slots + e * TOKENS;

    extern __shared__ char smem[];
    const uint32_t sb = smem_u32(smem);
    const int tid = threadIdx.x;
    const int lane = tid & 31;
    const int wid = tid >> 5;
    const int wm = wid & 3;       // m-block of 32
    const int wn = wid >> 2;      // n-block of 32

    const __nv_bfloat16* Ahi_base = (MODE == 0) ? g_xhi : g_h2hi;
    const __nv_bfloat16* Alo_base = (MODE == 0) ? g_xlo : g_h2lo;
    const __nv_bfloat16* Bhi_base = (MODE == 0) ? g_wfchi : g_wpjhi;
    const __nv_bfloat16* Blo_base = (MODE == 0) ? g_wfclo : g_wpjlo;

    // loader: thread covers rows r0l and r0l+64, 16B chunk c16 of 128B row
    const int c16 = tid & 7;
    const int r0l = tid >> 3;  // 0..63

    const __nv_bfloat16* aphi[2];
    const __nv_bfloat16* aplo[2];
    const __nv_bfloat16* bphi[2];
    const __nv_bfloat16* bplo[2];
    uint32_t asz[2];
    uint32_t swoff[2];
#pragma unroll
    for (int p = 0; p < 2; p++) {
        int row = r0l + 64 * p;
        swoff[p] = sw128((uint32_t)(row * 128 + c16 * 16));
        int m = m0 + row;
        if (m < cnt) {
            int slot = slots[m];
            int arow = (MODE == 0) ? (slot >> 1) : slot;
            aphi[p] = Ahi_base + (size_t)arow * K + c16 * 8;
            aplo[p] = Alo_base + (size_t)arow * K + c16 * 8;
            asz[p] = 16u;
        } else {
            aphi[p] = Ahi_base; aplo[p] = Alo_base; asz[p] = 0u;
        }
        size_t boff = ((size_t)e * NTOT + n0 + row) * K + c16 * 8;
        bphi[p] = Bhi_base + boff;
        bplo[p] = Blo_base + boff;
    }

    // ldmatrix address components (within-tile byte offsets before swizzle)
    const uint32_t a_row = wm * 32 + (lane & 15);
    const uint32_t a_kb = (uint32_t)((lane >> 4) << 4);
    const uint32_t b_row = wn * 32 + (lane & 7) + ((lane >> 4) << 3);
    const uint32_t b_kb = (uint32_t)(((lane >> 3) & 1) << 4);

    float acc[2][4][4];
#pragma unroll
    for (int i = 0; i < 2; i++)
#pragma unroll
        for (int j = 0; j < 4; j++)
#pragma unroll
            for (int q = 0; q < 4; q++) acc[i][j][q] = 0.f;

    constexpr int NK = K / 64;

    // issue slab 0 into stage 0
    {
        uint32_t base = sb;
#pragma unroll
        for (int p = 0; p < 2; p++) {
            cp16(base + OFF_AHI + swoff[p], aphi[p], asz[p]);
            cp16(base + OFF_ALO + swoff[p], aplo[p], asz[p]);
            cp16(base + OFF_BHI + swoff[p], bphi[p], 16u);
            cp16(base + OFF_BLO + swoff[p], bplo[p], 16u);
        }
        cp_commit();
    }

    for (int kt = 0; kt < NK; kt++) {
        if (kt + 1 < NK) {
            uint32_t base = sb + ((kt + 1) & 1) * STAGE_BYTES;
            int kn = (kt + 1) * 64;
#pragma unroll
            for (int p = 0; p < 2; p++) {
                cp16(base + OFF_AHI + swoff[p], aphi[p] + kn, asz[p]);
                cp16(base + OFF_ALO + swoff[p], aplo[p] + kn, asz[p]);
                cp16(base + OFF_BHI + swoff[p], bphi[p] + kn, 16u);
                cp16(base + OFF_BLO + swoff[p], bplo[p] + kn, 16u);
            }
            cp_commit();
            cp_wait<1>();
        } else {
            cp_wait<0>();
        }
        __syncthreads();

        const uint32_t base = sb + (kt & 1) * STAGE_BYTES;
#pragma unroll
        for (int c = 0; c < 4; c++) {
            const uint32_t kb = (uint32_t)(c * 32);
            uint32_t ah[2][4], al[2][4], bh[2][4], bl[2][4];
#pragma unroll
            for (int i = 0; i < 2; i++) {
                uint32_t off = sw128((a_row + 16 * i) * 128 + kb + a_kb);
                ldm_x4(ah[i], base + OFF_AHI + off);
                ldm_x4(al[i], base + OFF_ALO + off);
            }
#pragma unroll
            for (int jj = 0; jj < 2; jj++) {
                uint32_t off = sw128((b_row + 16 * jj) * 128 + kb + b_kb);
                ldm_x4(bh[jj], base + OFF_BHI + off);
                ldm_x4(bl[jj], base + OFF_BLO + off);
            }
#pragma unroll
            for (int i = 0; i < 2; i++)
#pragma unroll
                for (int j = 0; j < 4; j++) {
                    const uint32_t* bhp = &bh[j >> 1][(j & 1) * 2];
                    const uint32_t* blp = &bl[j >> 1][(j & 1) * 2];
                    mma_bf16(acc[i][j], ah[i], bhp);
                    mma_bf16(acc[i][j], ah[i], blp);
                    mma_bf16(acc[i][j], al[i], bhp);
                }
        }
        __syncthreads();
    }

    // epilogue
    const int gid = lane >> 2;
    const int tig = lane & 3;
#pragma unroll
    for (int i = 0; i < 2; i++) {
#pragma unroll
        for (int h = 0; h < 2; h++) {
            int mrow = m0 + wm * 32 + i * 16 + gid + 8 * h;
            if (mrow >= cnt) continue;
            int slot = slots[mrow];
            if (MODE == 0) {
                __nv_bfloat16* hr = g_h2hi + (size_t)slot * HIDDEN + n0;
                __nv_bfloat16* lr = g_h2lo + (size_t)slot * HIDDEN + n0;
#pragma unroll
                for (int j = 0; j < 4; j++) {
                    int col = wn * 32 + j * 8 + 2 * tig;
#pragma unroll
                    for (int q = 0; q < 2; q++) {
                        float v = acc[i][j][h * 2 + q];
                        v = fmaxf(v, 0.f);
                        v = v * v;
                        __nv_bfloat16 hh = __float2bfloat16(v);
                        __nv_bfloat16 ll = __float2bfloat16(v - __bfloat162float(hh));
                        hr[col + q] = hh;
                        lr[col + q] = ll;
                    }
                }
            } else {
                float wgt = g_w[slot];
                int token = slot >> 1;
                float* orow = out + (size_t)token * DIM + n0;
#pragma unroll
                for (int j = 0; j < 4; j++) {
                    int col = wn * 32 + j * 8 + 2 * tig;
                    atomicAdd(&orow[col + 0], wgt * acc[i][j][h * 2 + 0]);
                    atomicAdd(&orow[col + 1], wgt * acc[i][j][h * 2 + 1]);
                }
            }
        }
    }
}

// ---------------- launch ------------------------------------------------------
extern "C" void kernel_launch(void* const* d_in, const int* in_sizes, int n_in,
                              void* d_out, int out_size) {
    const float* x = (const float*)d_in[0];
    const float* Wr = (const float*)d_in[1];
    const float* Wfc = (const float*)d_in[2];
    const float* Wpj = (const float*)d_in[3];
    float* out = (float*)d_out;

    cudaFuncSetAttribute(moe_mma_gemm<DIM, HIDDEN, 0>,
                         cudaFuncAttributeMaxDynamicSharedMemorySize, SMEM_TOTAL);
    cudaFuncSetAttribute(moe_mma_gemm<HIDDEN, DIM, 1>,
                         cudaFuncAttributeMaxDynamicSharedMemorySize, SMEM_TOTAL);

    zero_cnt_kernel<<<1, 32>>>();
    zero_out_kernel<<<(out_size / 4 + 255) / 256, 256>>>(out, out_size);
    router_kernel<<<TOKENS / 8, 256>>>(x, Wr);

    int n4x = TOKENS * DIM / 4;
    int n4w = NE * HIDDEN * DIM / 4;
    split_kernel<0><<<(n4x + 255) / 256, 256>>>(x, n4x);
    split_kernel<1><<<(n4w + 255) / 256, 256>>>(Wfc, n4w);
    split_kernel<2><<<(n4w + 255) / 256, 256>>>(Wpj, n4w);

    // fc: N=HIDDEN, K=DIM
    moe_mma_gemm<DIM, HIDDEN, 0>
        <<<dim3(HIDDEN / 128, TOKENS / 128, NE), 512, SMEM_TOTAL>>>(out);
    // proj: N=DIM, K=HIDDEN  (accumulates directly into out)
    moe_mma_gemm<HIDDEN, DIM, 1>
        <<<dim3(DIM / 128, TOKENS / 128, NE), 512, SMEM_TOTAL>>>(out);
}